// round 15
// baseline (speedup 1.0000x reference)
#include <cuda_runtime.h>
#include <cuda_fp16.h>

#define GN 100000
#define GE 1600000
#define PADE (GE + 3 * GN)   // padded edge capacity (deg rounded up to mult of 4)
#define EPS 1e-5f
#define NB_SCAN 98           // ceil(GN/1024)

// ---------------- scratch (static device globals; no runtime alloc) --------
__device__ __half g_hA[(GN + 1) * 64];  // half gather source; row GN = zero pad row
__device__ __half g_hy0[GN * 64];       // half y0 (layer-0 pre-BN output)
__device__ float  g_bufA[GN * 64];      // fp32 aggregate (gather out -> gemm in)
__device__ float  g_bufB[GN * 64];      // fp32 y1
__device__ float  g_out_isqrt[GN + 1];  // [GN] = 0 (pad killer)
__device__ float  g_in_isqrt[GN];
__device__ float  g_stats[256];  // [0:64) sum, [64:128) sumsq, [128:192) scale, [192:256) shift
__device__ int    g_cnt_in[GN];
__device__ int    g_cnt_out[GN];
__device__ int    g_row[GN + 1];        // padded CSR offsets (each row mult of 4)
__device__ int    g_col[PADE];
__device__ int    g_fill[GN];
__device__ int    g_bsum[128];

// ---------------- init: counts zero, g_col sentinel, pad row zero ----------
__global__ void k_zero_int() {
    int i = blockIdx.x * blockDim.x + threadIdx.x;
    if (i < GN) { g_cnt_in[i] = 0; g_cnt_out[i] = 0; }
}

__global__ void k_init_pad() {
    int i = blockIdx.x * blockDim.x + threadIdx.x;
    if (i < PADE) g_col[i] = GN;                       // sentinel
    if (i < 64)  g_hA[GN * 64 + i] = __float2half(0.0f);
    if (i == 0)  g_out_isqrt[GN] = 0.0f;
}

// ---------------- degree counts (src/dst are int32) ----------------
__global__ void k_count(const int* __restrict__ src,
                        const int* __restrict__ dst) {
    int e = blockIdx.x * blockDim.x + threadIdx.x;
    if (e >= GE) return;
    int s = __ldg(&src[e]);
    int d = __ldg(&dst[e]);
    if ((unsigned)s < GN) atomicAdd(&g_cnt_out[s], 1);
    if ((unsigned)d < GN) atomicAdd(&g_cnt_in[d], 1);
}

// ---------------- CSR build over PADDED degrees ----------------
__global__ void k_scan_part() {
    __shared__ int red[1024];
    int gid = blockIdx.x * 1024 + threadIdx.x;
    int v = (gid < GN) ? ((g_cnt_in[gid] + 3) & ~3) : 0;
    red[threadIdx.x] = v;
    __syncthreads();
    for (int s = 512; s > 0; s >>= 1) {
        if (threadIdx.x < s) red[threadIdx.x] += red[threadIdx.x + s];
        __syncthreads();
    }
    if (threadIdx.x == 0) g_bsum[blockIdx.x] = red[0];
}

__global__ void k_scan_mid() {
    __shared__ int s[128];
    int v = (threadIdx.x < NB_SCAN) ? g_bsum[threadIdx.x] : 0;
    s[threadIdx.x] = v;
    __syncthreads();
    for (int off = 1; off < 128; off <<= 1) {
        int t = (threadIdx.x >= off) ? s[threadIdx.x - off] : 0;
        __syncthreads();
        s[threadIdx.x] += t;
        __syncthreads();
    }
    if (threadIdx.x < NB_SCAN) g_bsum[threadIdx.x] = s[threadIdx.x] - v;  // exclusive
    if (threadIdx.x == 127) g_row[GN] = s[127];
}

// scan_final + fused degree-isqrt (isqrt from ORIGINAL degree)
__global__ void k_scan_final() {
    __shared__ int s[1024];
    int gid = blockIdx.x * 1024 + threadIdx.x;
    int cnt = (gid < GN) ? g_cnt_in[gid] : 0;
    int pd = (cnt + 3) & ~3;
    s[threadIdx.x] = pd;
    __syncthreads();
    for (int off = 1; off < 1024; off <<= 1) {
        int t = (threadIdx.x >= off) ? s[threadIdx.x - off] : 0;
        __syncthreads();
        s[threadIdx.x] += t;
        __syncthreads();
    }
    if (gid < GN) {
        int r = s[threadIdx.x] - pd + g_bsum[blockIdx.x];
        g_row[gid]  = r;
        g_fill[gid] = r;
        g_in_isqrt[gid]  = rsqrtf(fmaxf((float)cnt, 1.0f));
        g_out_isqrt[gid] = rsqrtf(fmaxf((float)g_cnt_out[gid], 1.0f));
    }
}

__global__ void k_fill(const int* __restrict__ src,
                       const int* __restrict__ dst) {
    int e = blockIdx.x * blockDim.x + threadIdx.x;
    if (e >= GE) return;
    int s = __ldg(&src[e]);
    int d = __ldg(&dst[e]);
    if ((unsigned)s >= GN || (unsigned)d >= GN) return;
    int pos = atomicAdd(&g_fill[d], 1);
    g_col[pos] = s;
}

// ---------------- GEMM0: feat @ W0  [128 -> 64] -> g_hA (UNscaled) --------
// out_isqrt applied per-source in the gather. Runs overlapped with CSR build.
__global__ void k_gemm0(const float* __restrict__ feat,
                        const float* __restrict__ W) {
    __shared__ float sAT[16][132];
    __shared__ float sW[16][64];
    int base = blockIdx.x * 128;
    if (blockIdx.x == 0 && threadIdx.x < 128) g_stats[threadIdx.x] = 0.0f;
    int cgi = threadIdx.x & 15;
    int ngi = threadIdx.x >> 4;
    int cg = cgi * 4;
    float acc[8][4] = {};
    for (int kb = 0; kb < 8; kb++) {
        __syncthreads();
        #pragma unroll
        for (int it = 0; it < 2; it++) {
            int task = threadIdx.x + 256 * it;
            int node = task >> 2, k4 = task & 3;
            int gnode = base + node;
            float4 v = make_float4(0.f, 0.f, 0.f, 0.f);
            if (gnode < GN)
                v = __ldg((const float4*)&feat[gnode * 128 + kb * 16 + k4 * 4]);
            sAT[4 * k4 + 0][node] = v.x;
            sAT[4 * k4 + 1][node] = v.y;
            sAT[4 * k4 + 2][node] = v.z;
            sAT[4 * k4 + 3][node] = v.w;
        }
        {
            int kk = threadIdx.x >> 4, c4 = threadIdx.x & 15;
            *(float4*)&sW[kk][c4 * 4] =
                __ldg((const float4*)&W[(kb * 16 + kk) * 64 + c4 * 4]);
        }
        __syncthreads();
        #pragma unroll
        for (int kk = 0; kk < 16; kk++) {
            float4 a0 = *(const float4*)&sAT[kk][ngi * 8];
            float4 a1 = *(const float4*)&sAT[kk][ngi * 8 + 4];
            float4 w  = *(const float4*)&sW[kk][cg];
            float av[8] = {a0.x, a0.y, a0.z, a0.w, a1.x, a1.y, a1.z, a1.w};
            #pragma unroll
            for (int i = 0; i < 8; i++) {
                acc[i][0] += av[i] * w.x;
                acc[i][1] += av[i] * w.y;
                acc[i][2] += av[i] * w.z;
                acc[i][3] += av[i] * w.w;
            }
        }
    }
    #pragma unroll
    for (int i = 0; i < 8; i++) {
        int node = base + ngi * 8 + i;
        if (node < GN) {
            __half2 h0 = __floats2half2_rn(acc[i][0], acc[i][1]);
            __half2 h1 = __floats2half2_rn(acc[i][2], acc[i][3]);
            uint2 pk;
            pk.x = *(unsigned int*)&h0;
            pk.y = *(unsigned int*)&h1;
            *(uint2*)&g_hA[node * 64 + cg] = pk;
        }
    }
}

// ======== packed gathers: 4 edges per warp instruction ========
// lane = j*8 + c :  j = edge-in-group (0..3), c = feat chunk (feats 8c..8c+7)
// per group: 1 int4 idx LDG + 1 os LDG + 1 LDG.128 row load.

// ---------------- gather64 layer-0: sum os[s]*g_hA[s] -> y0 (+BN stats) ----
__global__ void k_gather64_l0(const float* __restrict__ bias) {
    __shared__ float s_s[64], s_q[64];
    if (threadIdx.x < 64) { s_s[threadIdx.x] = 0.0f; s_q[threadIdx.x] = 0.0f; }
    __syncthreads();
    int node = blockIdx.x * 8 + (threadIdx.x >> 5);
    int lane = threadIdx.x & 31;
    int j = lane >> 3, c = lane & 7;
    float a[8] = {};
    int beg = g_row[node], end = g_row[node + 1];
    for (int e = beg; e < end; e += 4) {
        int4 iv = __ldg((const int4*)&g_col[e]);
        int s = (j & 2) ? ((j & 1) ? iv.w : iv.z) : ((j & 1) ? iv.y : iv.x);
        float os = __ldg(&g_out_isqrt[s]);
        uint4 rv = __ldg((const uint4*)&g_hA[s * 64 + c * 8]);
        float2 f0 = __half22float2(*(__half2*)&rv.x);
        float2 f1 = __half22float2(*(__half2*)&rv.y);
        float2 f2 = __half22float2(*(__half2*)&rv.z);
        float2 f3 = __half22float2(*(__half2*)&rv.w);
        a[0] += f0.x * os; a[1] += f0.y * os;
        a[2] += f1.x * os; a[3] += f1.y * os;
        a[4] += f2.x * os; a[5] += f2.y * os;
        a[6] += f3.x * os; a[7] += f3.y * os;
    }
    #pragma unroll
    for (int k = 0; k < 8; k++) {
        a[k] += __shfl_xor_sync(0xffffffffu, a[k], 8);
        a[k] += __shfl_xor_sync(0xffffffffu, a[k], 16);
    }
    if (j == 0) {
        float isq = g_in_isqrt[node];
        float v[8];
        #pragma unroll
        for (int k = 0; k < 8; k++) {
            v[k] = a[k] * isq + __ldg(&bias[c * 8 + k]);
            atomicAdd(&s_s[c * 8 + k], v[k]);
            atomicAdd(&s_q[c * 8 + k], v[k] * v[k]);
        }
        __half2 h0 = __floats2half2_rn(v[0], v[1]);
        __half2 h1 = __floats2half2_rn(v[2], v[3]);
        __half2 h2 = __floats2half2_rn(v[4], v[5]);
        __half2 h3 = __floats2half2_rn(v[6], v[7]);
        uint4 pk;
        pk.x = *(unsigned int*)&h0; pk.y = *(unsigned int*)&h1;
        pk.z = *(unsigned int*)&h2; pk.w = *(unsigned int*)&h3;
        *(uint4*)&g_hy0[node * 64 + c * 8] = pk;
    }
    __syncthreads();
    if (threadIdx.x < 64) {
        atomicAdd(&g_stats[threadIdx.x],      s_s[threadIdx.x]);
        atomicAdd(&g_stats[64 + threadIdx.x], s_q[threadIdx.x]);
    }
}

// ---------------- finalize BN ----------------
__global__ void k_finalize_bn(const float* __restrict__ gamma,
                              const float* __restrict__ beta) {
    int f = threadIdx.x;
    if (f >= 64) return;
    float inv_n = 1.0f / (float)GN;
    float mu = g_stats[f] * inv_n;
    float var = g_stats[64 + f] * inv_n - mu * mu;
    float rstd = rsqrtf(var + EPS);
    float sc = __ldg(&gamma[f]) * rstd;
    g_stats[128 + f] = sc;
    g_stats[192 + f] = __ldg(&beta[f]) - mu * sc;
}

// ---------------- gather64 BN: sum max(sc*y0+sh,0)*os[s] -> bufA ----------
__global__ void k_gather64_bn() {
    if (blockIdx.x == 0 && threadIdx.x < 128) g_stats[threadIdx.x] = 0.0f;
    int node = blockIdx.x * 8 + (threadIdx.x >> 5);
    int lane = threadIdx.x & 31;
    int j = lane >> 3, c = lane & 7;
    float sc[8], sh[8];
    #pragma unroll
    for (int k = 0; k < 8; k++) {
        sc[k] = __ldg(&g_stats[128 + c * 8 + k]);
        sh[k] = __ldg(&g_stats[192 + c * 8 + k]);
    }
    float a[8] = {};
    int beg = g_row[node], end = g_row[node + 1];
    for (int e = beg; e < end; e += 4) {
        int4 iv = __ldg((const int4*)&g_col[e]);
        int s = (j & 2) ? ((j & 1) ? iv.w : iv.z) : ((j & 1) ? iv.y : iv.x);
        float os = __ldg(&g_out_isqrt[s]);
        uint4 rv = __ldg((const uint4*)&g_hy0[s * 64 + c * 8]);
        float2 f0 = __half22float2(*(__half2*)&rv.x);
        float2 f1 = __half22float2(*(__half2*)&rv.y);
        float2 f2 = __half22float2(*(__half2*)&rv.z);
        float2 f3 = __half22float2(*(__half2*)&rv.w);
        a[0] += fmaxf(f0.x * sc[0] + sh[0], 0.0f) * os;
        a[1] += fmaxf(f0.y * sc[1] + sh[1], 0.0f) * os;
        a[2] += fmaxf(f1.x * sc[2] + sh[2], 0.0f) * os;
        a[3] += fmaxf(f1.y * sc[3] + sh[3], 0.0f) * os;
        a[4] += fmaxf(f2.x * sc[4] + sh[4], 0.0f) * os;
        a[5] += fmaxf(f2.y * sc[5] + sh[5], 0.0f) * os;
        a[6] += fmaxf(f3.x * sc[6] + sh[6], 0.0f) * os;
        a[7] += fmaxf(f3.y * sc[7] + sh[7], 0.0f) * os;
    }
    #pragma unroll
    for (int k = 0; k < 8; k++) {
        a[k] += __shfl_xor_sync(0xffffffffu, a[k], 8);
        a[k] += __shfl_xor_sync(0xffffffffu, a[k], 16);
    }
    if (j == 0) {
        *(float4*)&g_bufA[node * 64 + c * 8]     = make_float4(a[0], a[1], a[2], a[3]);
        *(float4*)&g_bufA[node * 64 + c * 8 + 4] = make_float4(a[4], a[5], a[6], a[7]);
    }
}

// ---------------- GEMM1: bufA @ W1 then *in_isqrt + b1 -> bufB; BN stats --
__global__ void k_gemm1_stats(const float* __restrict__ W,
                              const float* __restrict__ bias) {
    __shared__ float sAT[16][132];
    __shared__ float sW[16][64];
    __shared__ float s_isq[128];
    __shared__ float s_s[64], s_q[64];
    int base = blockIdx.x * 128;
    for (int i = threadIdx.x; i < 128; i += 256) {
        int node = base + i;
        s_isq[i] = (node < GN) ? g_in_isqrt[node] : 0.0f;
    }
    if (threadIdx.x < 64) { s_s[threadIdx.x] = 0.0f; s_q[threadIdx.x] = 0.0f; }
    int cgi = threadIdx.x & 15;
    int ngi = threadIdx.x >> 4;
    int cg = cgi * 4;
    float acc[8][4] = {};
    for (int kb = 0; kb < 4; kb++) {
        __syncthreads();
        #pragma unroll
        for (int it = 0; it < 2; it++) {
            int task = threadIdx.x + 256 * it;
            int node = task >> 2, k4 = task & 3;
            int gnode = base + node;
            float4 v = make_float4(0.f, 0.f, 0.f, 0.f);
            if (gnode < GN)
                v = *(const float4*)&g_bufA[gnode * 64 + kb * 16 + k4 * 4];
            sAT[4 * k4 + 0][node] = v.x;
            sAT[4 * k4 + 1][node] = v.y;
            sAT[4 * k4 + 2][node] = v.z;
            sAT[4 * k4 + 3][node] = v.w;
        }
        {
            int kk = threadIdx.x >> 4, c4 = threadIdx.x & 15;
            *(float4*)&sW[kk][c4 * 4] =
                __ldg((const float4*)&W[(kb * 16 + kk) * 64 + c4 * 4]);
        }
        __syncthreads();
        #pragma unroll
        for (int kk = 0; kk < 16; kk++) {
            float4 a0 = *(const float4*)&sAT[kk][ngi * 8];
            float4 a1 = *(const float4*)&sAT[kk][ngi * 8 + 4];
            float4 w  = *(const float4*)&sW[kk][cg];
            float av[8] = {a0.x, a0.y, a0.z, a0.w, a1.x, a1.y, a1.z, a1.w};
            #pragma unroll
            for (int i = 0; i < 8; i++) {
                acc[i][0] += av[i] * w.x;
                acc[i][1] += av[i] * w.y;
                acc[i][2] += av[i] * w.z;
                acc[i][3] += av[i] * w.w;
            }
        }
    }
    float4 bv = __ldg((const float4*)&bias[cg]);
    float ls[4] = {}, lq[4] = {};
    #pragma unroll
    for (int i = 0; i < 8; i++) {
        int node = base + ngi * 8 + i;
        if (node < GN) {
            float is = s_isq[ngi * 8 + i];
            float v0 = acc[i][0] * is + bv.x;
            float v1 = acc[i][1] * is + bv.y;
            float v2 = acc[i][2] * is + bv.z;
            float v3 = acc[i][3] * is + bv.w;
            *(float4*)&g_bufB[node * 64 + cg] = make_float4(v0, v1, v2, v3);
            ls[0] += v0; lq[0] += v0 * v0;
            ls[1] += v1; lq[1] += v1 * v1;
            ls[2] += v2; lq[2] += v2 * v2;
            ls[3] += v3; lq[3] += v3 * v3;
        }
    }
    #pragma unroll
    for (int j = 0; j < 4; j++) {
        atomicAdd(&s_s[cg + j], ls[j]);
        atomicAdd(&s_q[cg + j], lq[j]);
    }
    __syncthreads();
    if (threadIdx.x < 64) {
        atomicAdd(&g_stats[threadIdx.x],      s_s[threadIdx.x]);
        atomicAdd(&g_stats[64 + threadIdx.x], s_q[threadIdx.x]);
    }
}

// ---------------- GEMM2: t1(bufB) @ W2  [64 -> 47] -> g_hA (stride 64) -----
__global__ void k_gemm2_bn(const float* __restrict__ W) {
    __shared__ float sAT[16][132];
    __shared__ float sW[16][64];
    __shared__ float s_os[128];
    __shared__ float s_sc[64], s_sh[64];
    int base = blockIdx.x * 128;
    for (int i = threadIdx.x; i < 128; i += 256) {
        int node = base + i;
        s_os[i] = (node < GN) ? g_out_isqrt[node] : 0.0f;
    }
    if (threadIdx.x < 64) {
        s_sc[threadIdx.x] = g_stats[128 + threadIdx.x];
        s_sh[threadIdx.x] = g_stats[192 + threadIdx.x];
    }
    int cgi = threadIdx.x & 15;
    int ngi = threadIdx.x >> 4;
    int cg = cgi * 4;
    float acc[8][4] = {};
    for (int kb = 0; kb < 4; kb++) {
        __syncthreads();
        #pragma unroll
        for (int it = 0; it < 2; it++) {
            int task = threadIdx.x + 256 * it;
            int node = task >> 2, k4 = task & 3;
            int gnode = base + node;
            float4 v = make_float4(0.f, 0.f, 0.f, 0.f);
            if (gnode < GN)
                v = *(const float4*)&g_bufB[gnode * 64 + kb * 16 + k4 * 4];
            float os = s_os[node];
            int k = kb * 16 + 4 * k4;
            sAT[4 * k4 + 0][node] = fmaxf(v.x * s_sc[k]     + s_sh[k],     0.0f) * os;
            sAT[4 * k4 + 1][node] = fmaxf(v.y * s_sc[k + 1] + s_sh[k + 1], 0.0f) * os;
            sAT[4 * k4 + 2][node] = fmaxf(v.z * s_sc[k + 2] + s_sh[k + 2], 0.0f) * os;
            sAT[4 * k4 + 3][node] = fmaxf(v.w * s_sc[k + 3] + s_sh[k + 3], 0.0f) * os;
        }
        #pragma unroll
        for (int it = 0; it < 4; it++) {
            int i = threadIdx.x + 256 * it;
            int kk = i >> 6, c = i & 63;
            float w = 0.0f;
            if (c < 47) w = __ldg(&W[(kb * 16 + kk) * 47 + c]);
            sW[kk][c] = w;
        }
        __syncthreads();
        #pragma unroll
        for (int kk = 0; kk < 16; kk++) {
            float4 a0 = *(const float4*)&sAT[kk][ngi * 8];
            float4 a1 = *(const float4*)&sAT[kk][ngi * 8 + 4];
            float4 w  = *(const float4*)&sW[kk][cg];
            float av[8] = {a0.x, a0.y, a0.z, a0.w, a1.x, a1.y, a1.z, a1.w};
            #pragma unroll
            for (int i = 0; i < 8; i++) {
                acc[i][0] += av[i] * w.x;
                acc[i][1] += av[i] * w.y;
                acc[i][2] += av[i] * w.z;
                acc[i][3] += av[i] * w.w;
            }
        }
    }
    #pragma unroll
    for (int i = 0; i < 8; i++) {
        int node = base + ngi * 8 + i;
        if (node < GN) {
            __half2 h0 = __floats2half2_rn(acc[i][0], acc[i][1]);
            __half2 h1 = __floats2half2_rn(acc[i][2], acc[i][3]);
            uint2 pk;
            pk.x = *(unsigned int*)&h0;
            pk.y = *(unsigned int*)&h1;
            *(uint2*)&g_hA[node * 64 + cg] = pk;
        }
    }
}

// ---------------- gather47 (packed) + final epilogue -> out ----------------
// sources pre-scaled by os in gemm2; pad row GN is zero; cols 47..63 zero.
__global__ void k_gather47(const float* __restrict__ b2,
                           float* __restrict__ out) {
    int node = blockIdx.x * 8 + (threadIdx.x >> 5);
    int lane = threadIdx.x & 31;
    int j = lane >> 3, c = lane & 7;
    float a[8] = {};
    int beg = g_row[node], end = g_row[node + 1];
    for (int e = beg; e < end; e += 4) {
        int4 iv = __ldg((const int4*)&g_col[e]);
        int s = (j & 2) ? ((j & 1) ? iv.w : iv.z) : ((j & 1) ? iv.y : iv.x);
        uint4 rv = __ldg((const uint4*)&g_hA[s * 64 + c * 8]);
        float2 f0 = __half22float2(*(__half2*)&rv.x);
        float2 f1 = __half22float2(*(__half2*)&rv.y);
        float2 f2 = __half22float2(*(__half2*)&rv.z);
        float2 f3 = __half22float2(*(__half2*)&rv.w);
        a[0] += f0.x; a[1] += f0.y;
        a[2] += f1.x; a[3] += f1.y;
        a[4] += f2.x; a[5] += f2.y;
        a[6] += f3.x; a[7] += f3.y;
    }
    #pragma unroll
    for (int k = 0; k < 8; k++) {
        a[k] += __shfl_xor_sync(0xffffffffu, a[k], 8);
        a[k] += __shfl_xor_sync(0xffffffffu, a[k], 16);
    }
    if (j == 0 && c < 6) {
        float isq = g_in_isqrt[node];
        #pragma unroll
        for (int k = 0; k < 8; k++) {
            int f = c * 8 + k;
            if (f < 47) out[node * 47 + f] = a[k] * isq + __ldg(&b2[f]);
        }
    }
}

// ============================================================================
extern "C" void kernel_launch(void* const* d_in, const int* in_sizes, int n_in,
                              void* d_out, int out_size) {
    const float* feat = (const float*)d_in[0];
    const int*   src  = (const int*)d_in[1];    // int32 (jax x64 disabled)
    const int*   dst  = (const int*)d_in[2];
    const float* W0 = (const float*)d_in[3];
    const float* b0 = (const float*)d_in[4];
    const float* W1 = (const float*)d_in[5];
    const float* b1 = (const float*)d_in[6];
    const float* W2 = (const float*)d_in[7];
    const float* b2 = (const float*)d_in[8];
    const float* gamma0 = (const float*)d_in[9];
    const float* beta0  = (const float*)d_in[10];
    const float* gamma1 = (const float*)d_in[11];
    const float* beta1  = (const float*)d_in[12];
    float* out = (float*)d_out;

    const int GB = 12500;              // gather blocks: 8 nodes each
    const int MB = (GN + 127) / 128;   // gemm blocks: 128 nodes each

    // side stream + events (created once; reused every call, capture-safe)
    static cudaStream_t s_side = nullptr;
    static cudaEvent_t  s_ev0 = nullptr, s_ev1 = nullptr;
    if (s_side == nullptr) {
        cudaStreamCreateWithFlags(&s_side, cudaStreamNonBlocking);
        cudaEventCreateWithFlags(&s_ev0, cudaEventDisableTiming);
        cudaEventCreateWithFlags(&s_ev1, cudaEventDisableTiming);
    }

    // ---- fork: gemm0 (feat-only) on side stream, CSR build on main ----
    cudaEventRecord(s_ev0, 0);
    cudaStreamWaitEvent(s_side, s_ev0, 0);
    k_gemm0<<<MB, 256, 0, s_side>>>(feat, W0);   // feat -> g_hA (+zero stats)
    cudaEventRecord(s_ev1, s_side);

    // ---- CSR build (padded) + degree isqrt (main stream) ----
    k_zero_int<<<(GN + 255) / 256, 256>>>();
    k_init_pad<<<(PADE + 255) / 256, 256>>>();
    k_count<<<(GE + 255) / 256, 256>>>(src, dst);
    k_scan_part<<<NB_SCAN, 1024>>>();
    k_scan_mid<<<1, 128>>>();
    k_scan_final<<<NB_SCAN, 1024>>>();
    k_fill<<<(GE + 255) / 256, 256>>>(src, dst);

    // ---- join: gather needs both CSR and gemm0 output ----
    cudaStreamWaitEvent(0, s_ev1, 0);

    // ---- layer 0: packed gather w/ fused os+bias+stats ----
    k_gather64_l0<<<GB, 256>>>(b0);              // g_hA -> g_hy0 (y0 + stats)
    k_finalize_bn<<<1, 64>>>(gamma0, beta0);

    // ---- layer 1: packed gather w/ fused BN0 transform, matmul ----
    k_gather64_bn<<<GB, 256>>>();                // g_hy0 -> bufA (+zero stats)
    k_gemm1_stats<<<MB, 256>>>(W1, b1);          // bufA -> bufB (y1 + stats)
    k_finalize_bn<<<1, 64>>>(gamma1, beta1);

    // ---- layer 2: matmul w/ fused BN1 transform, packed gather ----
    k_gemm2_bn<<<MB, 256>>>(W2);                 // bufB -> g_hA (stride 64)
    k_gather47<<<GB, 256>>>(b2, out);            // g_hA -> out
}

// round 16
// speedup vs baseline: 1.0477x; 1.0477x over previous
#include <cuda_runtime.h>
#include <cuda_fp16.h>

#define GN 100000
#define GE 1600000
#define EPS 1e-5f
#define NB_SCAN 98   // ceil(GN/1024)

// ---------------- scratch (static device globals; no runtime alloc) --------
__device__ __half g_hA[GN * 64];    // half gather source (gemm0 out, later gemm2 out)
__device__ __half g_hy0[GN * 64];   // half y0 (layer-0 pre-BN output)
__device__ float  g_bufA[GN * 64];  // fp32 aggregate (gather output -> gemm input)
__device__ float  g_bufB[GN * 64];  // fp32 y1
__device__ float  g_out_isqrt[GN];
__device__ float  g_in_isqrt[GN];
__device__ float  g_stats[256];  // [0:64) sum, [64:128) sumsq, [128:192) scale, [192:256) shift
__device__ int    g_cnt_in[GN];
__device__ int    g_cnt_out[GN];
__device__ int    g_row[GN + 1];
__device__ int    g_col[GE];
__device__ int    g_fill[GN];
__device__ int    g_bsum[128];

// ---------------- zero helper ----------------
__global__ void k_zero_int() {
    int i = blockIdx.x * blockDim.x + threadIdx.x;
    if (i < GN) { g_cnt_in[i] = 0; g_cnt_out[i] = 0; }
}

// ---------------- degree counts: 4 edges per thread via int4 --------------
__global__ void k_count(const int* __restrict__ src,
                        const int* __restrict__ dst) {
    int t = blockIdx.x * blockDim.x + threadIdx.x;   // GE/4 = 400000 tasks
    if (t >= GE / 4) return;
    int4 sv = __ldg((const int4*)&src[4 * t]);
    int4 dv = __ldg((const int4*)&dst[4 * t]);
    if ((unsigned)sv.x < GN) atomicAdd(&g_cnt_out[sv.x], 1);
    if ((unsigned)sv.y < GN) atomicAdd(&g_cnt_out[sv.y], 1);
    if ((unsigned)sv.z < GN) atomicAdd(&g_cnt_out[sv.z], 1);
    if ((unsigned)sv.w < GN) atomicAdd(&g_cnt_out[sv.w], 1);
    if ((unsigned)dv.x < GN) atomicAdd(&g_cnt_in[dv.x], 1);
    if ((unsigned)dv.y < GN) atomicAdd(&g_cnt_in[dv.y], 1);
    if ((unsigned)dv.z < GN) atomicAdd(&g_cnt_in[dv.z], 1);
    if ((unsigned)dv.w < GN) atomicAdd(&g_cnt_in[dv.w], 1);
}

// ---------------- CSR build: scan of g_cnt_in -> g_row, fill g_col --------
__global__ void k_scan_part() {
    __shared__ int red[1024];
    int gid = blockIdx.x * 1024 + threadIdx.x;
    int v = (gid < GN) ? g_cnt_in[gid] : 0;
    red[threadIdx.x] = v;
    __syncthreads();
    for (int s = 512; s > 0; s >>= 1) {
        if (threadIdx.x < s) red[threadIdx.x] += red[threadIdx.x + s];
        __syncthreads();
    }
    if (threadIdx.x == 0) g_bsum[blockIdx.x] = red[0];
}

// parallel 128-wide scan of block sums
__global__ void k_scan_mid() {
    __shared__ int s[128];
    int v = (threadIdx.x < NB_SCAN) ? g_bsum[threadIdx.x] : 0;
    s[threadIdx.x] = v;
    __syncthreads();
    for (int off = 1; off < 128; off <<= 1) {
        int t = (threadIdx.x >= off) ? s[threadIdx.x - off] : 0;
        __syncthreads();
        s[threadIdx.x] += t;
        __syncthreads();
    }
    if (threadIdx.x < NB_SCAN) g_bsum[threadIdx.x] = s[threadIdx.x] - v;  // exclusive
    if (threadIdx.x == 127) g_row[GN] = s[127];
}

// scan_final + fused degree-isqrt
__global__ void k_scan_final() {
    __shared__ int s[1024];
    int gid = blockIdx.x * 1024 + threadIdx.x;
    int v = (gid < GN) ? g_cnt_in[gid] : 0;
    s[threadIdx.x] = v;
    __syncthreads();
    for (int off = 1; off < 1024; off <<= 1) {
        int t = (threadIdx.x >= off) ? s[threadIdx.x - off] : 0;
        __syncthreads();
        s[threadIdx.x] += t;
        __syncthreads();
    }
    if (gid < GN) {
        int r = s[threadIdx.x] - v + g_bsum[blockIdx.x];
        g_row[gid]  = r;
        g_fill[gid] = r;
        g_in_isqrt[gid]  = rsqrtf(fmaxf((float)v, 1.0f));
        g_out_isqrt[gid] = rsqrtf(fmaxf((float)g_cnt_out[gid], 1.0f));
    }
}

// ---------------- fill: 4 edges per thread via int4 ----------------
__global__ void k_fill(const int* __restrict__ src,
                       const int* __restrict__ dst) {
    int t = blockIdx.x * blockDim.x + threadIdx.x;
    if (t >= GE / 4) return;
    int4 sv = __ldg((const int4*)&src[4 * t]);
    int4 dv = __ldg((const int4*)&dst[4 * t]);
    if ((unsigned)sv.x < GN && (unsigned)dv.x < GN)
        g_col[atomicAdd(&g_fill[dv.x], 1)] = sv.x;
    if ((unsigned)sv.y < GN && (unsigned)dv.y < GN)
        g_col[atomicAdd(&g_fill[dv.y], 1)] = sv.y;
    if ((unsigned)sv.z < GN && (unsigned)dv.z < GN)
        g_col[atomicAdd(&g_fill[dv.z], 1)] = sv.z;
    if ((unsigned)sv.w < GN && (unsigned)dv.w < GN)
        g_col[atomicAdd(&g_fill[dv.w], 1)] = sv.w;
}

// ---------------- GEMM0: feat @ W0  [128 -> 64] -> g_hA (UNscaled) --------
// out_isqrt applied per-source in the gather. Runs overlapped with CSR build.
__global__ void k_gemm0(const float* __restrict__ feat,
                        const float* __restrict__ W) {
    __shared__ float sAT[16][132];
    __shared__ float sW[16][64];
    int base = blockIdx.x * 128;
    if (blockIdx.x == 0 && threadIdx.x < 128) g_stats[threadIdx.x] = 0.0f;
    int cgi = threadIdx.x & 15;
    int ngi = threadIdx.x >> 4;
    int cg = cgi * 4;
    float acc[8][4] = {};
    for (int kb = 0; kb < 8; kb++) {
        __syncthreads();
        #pragma unroll
        for (int it = 0; it < 2; it++) {
            int task = threadIdx.x + 256 * it;
            int node = task >> 2, k4 = task & 3;
            int gnode = base + node;
            float4 v = make_float4(0.f, 0.f, 0.f, 0.f);
            if (gnode < GN)
                v = __ldg((const float4*)&feat[gnode * 128 + kb * 16 + k4 * 4]);
            sAT[4 * k4 + 0][node] = v.x;
            sAT[4 * k4 + 1][node] = v.y;
            sAT[4 * k4 + 2][node] = v.z;
            sAT[4 * k4 + 3][node] = v.w;
        }
        {
            int kk = threadIdx.x >> 4, c4 = threadIdx.x & 15;
            *(float4*)&sW[kk][c4 * 4] =
                __ldg((const float4*)&W[(kb * 16 + kk) * 64 + c4 * 4]);
        }
        __syncthreads();
        #pragma unroll
        for (int kk = 0; kk < 16; kk++) {
            float4 a0 = *(const float4*)&sAT[kk][ngi * 8];
            float4 a1 = *(const float4*)&sAT[kk][ngi * 8 + 4];
            float4 w  = *(const float4*)&sW[kk][cg];
            float av[8] = {a0.x, a0.y, a0.z, a0.w, a1.x, a1.y, a1.z, a1.w};
            #pragma unroll
            for (int i = 0; i < 8; i++) {
                acc[i][0] += av[i] * w.x;
                acc[i][1] += av[i] * w.y;
                acc[i][2] += av[i] * w.z;
                acc[i][3] += av[i] * w.w;
            }
        }
    }
    #pragma unroll
    for (int i = 0; i < 8; i++) {
        int node = base + ngi * 8 + i;
        if (node < GN) {
            __half2 h0 = __floats2half2_rn(acc[i][0], acc[i][1]);
            __half2 h1 = __floats2half2_rn(acc[i][2], acc[i][3]);
            uint2 pk;
            pk.x = *(unsigned int*)&h0;
            pk.y = *(unsigned int*)&h1;
            *(uint2*)&g_hA[node * 64 + cg] = pk;
        }
    }
}

// ---------------- gather, 64 feats (half src, *os[src]), layer0 epilogue --
// g_hA -> g_hy0 (+BN stats)
__global__ void k_gather64_l0(const float* __restrict__ bias) {
    __shared__ float s_s[64], s_q[64];
    if (threadIdx.x < 64) { s_s[threadIdx.x] = 0.0f; s_q[threadIdx.x] = 0.0f; }
    __syncthreads();
    int node = blockIdx.x * 8 + (threadIdx.x >> 5);
    int lane = threadIdx.x & 31;
    if (node < GN) {
        int beg = g_row[node], end = g_row[node + 1];
        float ax0 = 0, ay0 = 0, ax1 = 0, ay1 = 0, ax2 = 0, ay2 = 0, ax3 = 0, ay3 = 0;
        int e = beg;
        for (; e + 3 < end; e += 4) {
            int s0 = __ldg(&g_col[e]);
            int s1 = __ldg(&g_col[e + 1]);
            int s2 = __ldg(&g_col[e + 2]);
            int s3 = __ldg(&g_col[e + 3]);
            float o0 = __ldg(&g_out_isqrt[s0]);
            float o1 = __ldg(&g_out_isqrt[s1]);
            float o2 = __ldg(&g_out_isqrt[s2]);
            float o3 = __ldg(&g_out_isqrt[s3]);
            float2 v0 = __half22float2(*(const __half2*)&g_hA[s0 * 64 + 2 * lane]);
            float2 v1 = __half22float2(*(const __half2*)&g_hA[s1 * 64 + 2 * lane]);
            float2 v2 = __half22float2(*(const __half2*)&g_hA[s2 * 64 + 2 * lane]);
            float2 v3 = __half22float2(*(const __half2*)&g_hA[s3 * 64 + 2 * lane]);
            ax0 += v0.x * o0; ay0 += v0.y * o0;
            ax1 += v1.x * o1; ay1 += v1.y * o1;
            ax2 += v2.x * o2; ay2 += v2.y * o2;
            ax3 += v3.x * o3; ay3 += v3.y * o3;
        }
        for (; e < end; e++) {
            int s0 = __ldg(&g_col[e]);
            float o0 = __ldg(&g_out_isqrt[s0]);
            float2 v0 = __half22float2(*(const __half2*)&g_hA[s0 * 64 + 2 * lane]);
            ax0 += v0.x * o0; ay0 += v0.y * o0;
        }
        float ax = (ax0 + ax1) + (ax2 + ax3);
        float ay = (ay0 + ay1) + (ay2 + ay3);
        float isq = g_in_isqrt[node];
        float v0 = ax * isq + __ldg(&bias[2 * lane]);
        float v1 = ay * isq + __ldg(&bias[2 * lane + 1]);
        *(__half2*)&g_hy0[node * 64 + 2 * lane] = __floats2half2_rn(v0, v1);
        atomicAdd(&s_s[2 * lane], v0);      atomicAdd(&s_s[2 * lane + 1], v1);
        atomicAdd(&s_q[2 * lane], v0 * v0); atomicAdd(&s_q[2 * lane + 1], v1 * v1);
    }
    __syncthreads();
    if (threadIdx.x < 64) {
        atomicAdd(&g_stats[threadIdx.x],      s_s[threadIdx.x]);
        atomicAdd(&g_stats[64 + threadIdx.x], s_q[threadIdx.x]);
    }
}

// ---------------- finalize BN ----------------
__global__ void k_finalize_bn(const float* __restrict__ gamma,
                              const float* __restrict__ beta) {
    int f = threadIdx.x;
    if (f >= 64) return;
    float inv_n = 1.0f / (float)GN;
    float mu = g_stats[f] * inv_n;
    float var = g_stats[64 + f] * inv_n - mu * mu;
    float rstd = rsqrtf(var + EPS);
    float sc = __ldg(&gamma[f]) * rstd;
    g_stats[128 + f] = sc;
    g_stats[192 + f] = __ldg(&beta[f]) - mu * sc;
}

// ---------------- gather64 w/ fused BN+ReLU+out_isqrt on SOURCE elements --
// g_hy0 -> bufA (fp32)
__global__ void k_gather64_bn() {
    if (blockIdx.x == 0 && threadIdx.x < 128) g_stats[threadIdx.x] = 0.0f;
    int node = blockIdx.x * 8 + (threadIdx.x >> 5);
    int lane = threadIdx.x & 31;
    if (node >= GN) return;
    float sc0 = g_stats[128 + 2 * lane], sc1 = g_stats[128 + 2 * lane + 1];
    float sh0 = g_stats[192 + 2 * lane], sh1 = g_stats[192 + 2 * lane + 1];
    int beg = g_row[node], end = g_row[node + 1];
    float ax0 = 0, ay0 = 0, ax1 = 0, ay1 = 0, ax2 = 0, ay2 = 0, ax3 = 0, ay3 = 0;
    int e = beg;
    for (; e + 3 < end; e += 4) {
        int s0 = __ldg(&g_col[e]);
        int s1 = __ldg(&g_col[e + 1]);
        int s2 = __ldg(&g_col[e + 2]);
        int s3 = __ldg(&g_col[e + 3]);
        float o0 = __ldg(&g_out_isqrt[s0]);
        float o1 = __ldg(&g_out_isqrt[s1]);
        float o2 = __ldg(&g_out_isqrt[s2]);
        float o3 = __ldg(&g_out_isqrt[s3]);
        float2 v0 = __half22float2(*(const __half2*)&g_hy0[s0 * 64 + 2 * lane]);
        float2 v1 = __half22float2(*(const __half2*)&g_hy0[s1 * 64 + 2 * lane]);
        float2 v2 = __half22float2(*(const __half2*)&g_hy0[s2 * 64 + 2 * lane]);
        float2 v3 = __half22float2(*(const __half2*)&g_hy0[s3 * 64 + 2 * lane]);
        ax0 += fmaxf(v0.x * sc0 + sh0, 0.0f) * o0;
        ay0 += fmaxf(v0.y * sc1 + sh1, 0.0f) * o0;
        ax1 += fmaxf(v1.x * sc0 + sh0, 0.0f) * o1;
        ay1 += fmaxf(v1.y * sc1 + sh1, 0.0f) * o1;
        ax2 += fmaxf(v2.x * sc0 + sh0, 0.0f) * o2;
        ay2 += fmaxf(v2.y * sc1 + sh1, 0.0f) * o2;
        ax3 += fmaxf(v3.x * sc0 + sh0, 0.0f) * o3;
        ay3 += fmaxf(v3.y * sc1 + sh1, 0.0f) * o3;
    }
    for (; e < end; e++) {
        int s0 = __ldg(&g_col[e]);
        float o0 = __ldg(&g_out_isqrt[s0]);
        float2 v0 = __half22float2(*(const __half2*)&g_hy0[s0 * 64 + 2 * lane]);
        ax0 += fmaxf(v0.x * sc0 + sh0, 0.0f) * o0;
        ay0 += fmaxf(v0.y * sc1 + sh1, 0.0f) * o0;
    }
    float ax = (ax0 + ax1) + (ax2 + ax3);
    float ay = (ay0 + ay1) + (ay2 + ay3);
    *(float2*)&g_bufA[node * 64 + 2 * lane] = make_float2(ax, ay);
}

// ---------------- GEMM1: bufA @ W1 then *in_isqrt + b1 -> bufB; BN stats --
__global__ void k_gemm1_stats(const float* __restrict__ W,
                              const float* __restrict__ bias) {
    __shared__ float sAT[16][132];
    __shared__ float sW[16][64];
    __shared__ float s_isq[128];
    __shared__ float s_s[64], s_q[64];
    int base = blockIdx.x * 128;
    for (int i = threadIdx.x; i < 128; i += 256) {
        int node = base + i;
        s_isq[i] = (node < GN) ? g_in_isqrt[node] : 0.0f;
    }
    if (threadIdx.x < 64) { s_s[threadIdx.x] = 0.0f; s_q[threadIdx.x] = 0.0f; }
    int cgi = threadIdx.x & 15;
    int ngi = threadIdx.x >> 4;
    int cg = cgi * 4;
    float acc[8][4] = {};
    for (int kb = 0; kb < 4; kb++) {
        __syncthreads();
        #pragma unroll
        for (int it = 0; it < 2; it++) {
            int task = threadIdx.x + 256 * it;
            int node = task >> 2, k4 = task & 3;
            int gnode = base + node;
            float4 v = make_float4(0.f, 0.f, 0.f, 0.f);
            if (gnode < GN)
                v = *(const float4*)&g_bufA[gnode * 64 + kb * 16 + k4 * 4];
            sAT[4 * k4 + 0][node] = v.x;
            sAT[4 * k4 + 1][node] = v.y;
            sAT[4 * k4 + 2][node] = v.z;
            sAT[4 * k4 + 3][node] = v.w;
        }
        {
            int kk = threadIdx.x >> 4, c4 = threadIdx.x & 15;
            *(float4*)&sW[kk][c4 * 4] =
                __ldg((const float4*)&W[(kb * 16 + kk) * 64 + c4 * 4]);
        }
        __syncthreads();
        #pragma unroll
        for (int kk = 0; kk < 16; kk++) {
            float4 a0 = *(const float4*)&sAT[kk][ngi * 8];
            float4 a1 = *(const float4*)&sAT[kk][ngi * 8 + 4];
            float4 w  = *(const float4*)&sW[kk][cg];
            float av[8] = {a0.x, a0.y, a0.z, a0.w, a1.x, a1.y, a1.z, a1.w};
            #pragma unroll
            for (int i = 0; i < 8; i++) {
                acc[i][0] += av[i] * w.x;
                acc[i][1] += av[i] * w.y;
                acc[i][2] += av[i] * w.z;
                acc[i][3] += av[i] * w.w;
            }
        }
    }
    float4 bv = __ldg((const float4*)&bias[cg]);
    float ls[4] = {}, lq[4] = {};
    #pragma unroll
    for (int i = 0; i < 8; i++) {
        int node = base + ngi * 8 + i;
        if (node < GN) {
            float is = s_isq[ngi * 8 + i];
            float v0 = acc[i][0] * is + bv.x;
            float v1 = acc[i][1] * is + bv.y;
            float v2 = acc[i][2] * is + bv.z;
            float v3 = acc[i][3] * is + bv.w;
            *(float4*)&g_bufB[node * 64 + cg] = make_float4(v0, v1, v2, v3);
            ls[0] += v0; lq[0] += v0 * v0;
            ls[1] += v1; lq[1] += v1 * v1;
            ls[2] += v2; lq[2] += v2 * v2;
            ls[3] += v3; lq[3] += v3 * v3;
        }
    }
    #pragma unroll
    for (int j = 0; j < 4; j++) {
        atomicAdd(&s_s[cg + j], ls[j]);
        atomicAdd(&s_q[cg + j], lq[j]);
    }
    __syncthreads();
    if (threadIdx.x < 64) {
        atomicAdd(&g_stats[threadIdx.x],      s_s[threadIdx.x]);
        atomicAdd(&g_stats[64 + threadIdx.x], s_q[threadIdx.x]);
    }
}

// ---------------- GEMM2: t1(bufB) @ W2  [64 -> 47] -> g_hA (stride 64) -----
__global__ void k_gemm2_bn(const float* __restrict__ W) {
    __shared__ float sAT[16][132];
    __shared__ float sW[16][64];
    __shared__ float s_os[128];
    __shared__ float s_sc[64], s_sh[64];
    int base = blockIdx.x * 128;
    for (int i = threadIdx.x; i < 128; i += 256) {
        int node = base + i;
        s_os[i] = (node < GN) ? g_out_isqrt[node] : 0.0f;
    }
    if (threadIdx.x < 64) {
        s_sc[threadIdx.x] = g_stats[128 + threadIdx.x];
        s_sh[threadIdx.x] = g_stats[192 + threadIdx.x];
    }
    int cgi = threadIdx.x & 15;
    int ngi = threadIdx.x >> 4;
    int cg = cgi * 4;
    float acc[8][4] = {};
    for (int kb = 0; kb < 4; kb++) {
        __syncthreads();
        #pragma unroll
        for (int it = 0; it < 2; it++) {
            int task = threadIdx.x + 256 * it;
            int node = task >> 2, k4 = task & 3;
            int gnode = base + node;
            float4 v = make_float4(0.f, 0.f, 0.f, 0.f);
            if (gnode < GN)
                v = *(const float4*)&g_bufB[gnode * 64 + kb * 16 + k4 * 4];
            float os = s_os[node];
            int k = kb * 16 + 4 * k4;
            sAT[4 * k4 + 0][node] = fmaxf(v.x * s_sc[k]     + s_sh[k],     0.0f) * os;
            sAT[4 * k4 + 1][node] = fmaxf(v.y * s_sc[k + 1] + s_sh[k + 1], 0.0f) * os;
            sAT[4 * k4 + 2][node] = fmaxf(v.z * s_sc[k + 2] + s_sh[k + 2], 0.0f) * os;
            sAT[4 * k4 + 3][node] = fmaxf(v.w * s_sc[k + 3] + s_sh[k + 3], 0.0f) * os;
        }
        #pragma unroll
        for (int it = 0; it < 4; it++) {
            int i = threadIdx.x + 256 * it;
            int kk = i >> 6, c = i & 63;
            float w = 0.0f;
            if (c < 47) w = __ldg(&W[(kb * 16 + kk) * 47 + c]);
            sW[kk][c] = w;
        }
        __syncthreads();
        #pragma unroll
        for (int kk = 0; kk < 16; kk++) {
            float4 a0 = *(const float4*)&sAT[kk][ngi * 8];
            float4 a1 = *(const float4*)&sAT[kk][ngi * 8 + 4];
            float4 w  = *(const float4*)&sW[kk][cg];
            float av[8] = {a0.x, a0.y, a0.z, a0.w, a1.x, a1.y, a1.z, a1.w};
            #pragma unroll
            for (int i = 0; i < 8; i++) {
                acc[i][0] += av[i] * w.x;
                acc[i][1] += av[i] * w.y;
                acc[i][2] += av[i] * w.z;
                acc[i][3] += av[i] * w.w;
            }
        }
    }
    #pragma unroll
    for (int i = 0; i < 8; i++) {
        int node = base + ngi * 8 + i;
        if (node < GN) {
            __half2 h0 = __floats2half2_rn(acc[i][0], acc[i][1]);
            __half2 h1 = __floats2half2_rn(acc[i][2], acc[i][3]);
            uint2 pk;
            pk.x = *(unsigned int*)&h0;
            pk.y = *(unsigned int*)&h1;
            *(uint2*)&g_hA[node * 64 + cg] = pk;
        }
    }
}

// ---------------- gather, 47 feats (half src) + final epilogue -> out -----
__global__ void k_gather47(const float* __restrict__ b2,
                           float* __restrict__ out) {
    int node = blockIdx.x * 8 + (threadIdx.x >> 5);
    int lane = threadIdx.x & 31;
    if (node >= GN) return;
    int beg = g_row[node], end = g_row[node + 1];
    int f = 2 * lane;
    float ax0 = 0, ay0 = 0, ax1 = 0, ay1 = 0, ax2 = 0, ay2 = 0, ax3 = 0, ay3 = 0;
    if (f < 46) {
        int e = beg;
        for (; e + 3 < end; e += 4) {
            int s0 = __ldg(&g_col[e]);
            int s1 = __ldg(&g_col[e + 1]);
            int s2 = __ldg(&g_col[e + 2]);
            int s3 = __ldg(&g_col[e + 3]);
            float2 v0 = __half22float2(*(const __half2*)&g_hA[s0 * 64 + f]);
            float2 v1 = __half22float2(*(const __half2*)&g_hA[s1 * 64 + f]);
            float2 v2 = __half22float2(*(const __half2*)&g_hA[s2 * 64 + f]);
            float2 v3 = __half22float2(*(const __half2*)&g_hA[s3 * 64 + f]);
            ax0 += v0.x; ay0 += v0.y;
            ax1 += v1.x; ay1 += v1.y;
            ax2 += v2.x; ay2 += v2.y;
            ax3 += v3.x; ay3 += v3.y;
        }
        for (; e < end; e++) {
            int s0 = __ldg(&g_col[e]);
            float2 v0 = __half22float2(*(const __half2*)&g_hA[s0 * 64 + f]);
            ax0 += v0.x; ay0 += v0.y;
        }
        float isq = g_in_isqrt[node];
        out[node * 47 + f]     = ((ax0 + ax1) + (ax2 + ax3)) * isq + __ldg(&b2[f]);
        out[node * 47 + f + 1] = ((ay0 + ay1) + (ay2 + ay3)) * isq + __ldg(&b2[f + 1]);
    } else if (f == 46) {
        for (int e = beg; e < end; e++) {
            int s = __ldg(&g_col[e]);
            ax0 += __half2float(g_hA[s * 64 + 46]);
        }
        out[node * 47 + 46] = ax0 * g_in_isqrt[node] + __ldg(&b2[46]);
    }
}

// ============================================================================
extern "C" void kernel_launch(void* const* d_in, const int* in_sizes, int n_in,
                              void* d_out, int out_size) {
    const float* feat = (const float*)d_in[0];
    const int*   src  = (const int*)d_in[1];    // int32 (jax x64 disabled)
    const int*   dst  = (const int*)d_in[2];
    const float* W0 = (const float*)d_in[3];
    const float* b0 = (const float*)d_in[4];
    const float* W1 = (const float*)d_in[5];
    const float* b1 = (const float*)d_in[6];
    const float* W2 = (const float*)d_in[7];
    const float* b2 = (const float*)d_in[8];
    const float* gamma0 = (const float*)d_in[9];
    const float* beta0  = (const float*)d_in[10];
    const float* gamma1 = (const float*)d_in[11];
    const float* beta1  = (const float*)d_in[12];
    float* out = (float*)d_out;

    const int GB = 12500;              // gather blocks: 8 nodes each
    const int MB = (GN + 127) / 128;   // gemm blocks: 128 nodes each
    const int EB4 = (GE / 4 + 255) / 256;  // 4-edges-per-thread blocks

    // side stream + events (created once; reused every call, capture-safe)
    static cudaStream_t s_side = nullptr;
    static cudaEvent_t  s_ev0 = nullptr, s_ev1 = nullptr;
    if (s_side == nullptr) {
        cudaStreamCreateWithFlags(&s_side, cudaStreamNonBlocking);
        cudaEventCreateWithFlags(&s_ev0, cudaEventDisableTiming);
        cudaEventCreateWithFlags(&s_ev1, cudaEventDisableTiming);
    }

    // ---- fork: gemm0 (feat-only) on side stream, CSR build on main ----
    cudaEventRecord(s_ev0, 0);
    cudaStreamWaitEvent(s_side, s_ev0, 0);
    k_gemm0<<<MB, 256, 0, s_side>>>(feat, W0);   // feat -> g_hA (+zero stats)
    cudaEventRecord(s_ev1, s_side);

    // ---- CSR build + degree isqrt (main stream) ----
    k_zero_int<<<(GN + 255) / 256, 256>>>();
    k_count<<<EB4, 256>>>(src, dst);
    k_scan_part<<<NB_SCAN, 1024>>>();
    k_scan_mid<<<1, 128>>>();
    k_scan_final<<<NB_SCAN, 1024>>>();      // also computes isqrt + fill cursors
    k_fill<<<EB4, 256>>>(src, dst);

    // ---- join: gather needs both CSR and gemm0 output ----
    cudaStreamWaitEvent(0, s_ev1, 0);

    // ---- layer 0: gather w/ fused os[src]+bias+stats epilogue ----
    k_gather64_l0<<<GB, 256>>>(b0);              // g_hA -> g_hy0 (y0 + stats)
    k_finalize_bn<<<1, 64>>>(gamma0, beta0);

    // ---- layer 1: gather w/ fused BN0 transform, matmul (64 -> 64) ----
    k_gather64_bn<<<GB, 256>>>();                // g_hy0 -> bufA (+zero stats)
    k_gemm1_stats<<<MB, 256>>>(W1, b1);          // bufA -> bufB (y1 + stats)
    k_finalize_bn<<<1, 64>>>(gamma1, beta1);

    // ---- layer 2: matmul w/ fused BN1 transform (64 -> 47) -> half, gather --
    k_gemm2_bn<<<MB, 256>>>(W2);                 // bufB -> g_hA (stride 64)
    k_gather47<<<GB, 256>>>(b2, out);            // g_hA -> out
}

// round 17
// speedup vs baseline: 1.0561x; 1.0080x over previous
#include <cuda_runtime.h>
#include <cuda_fp16.h>

#define GN 100000
#define GE 1600000
#define EPS 1e-5f
#define NB_SCAN 98   // ceil(GN/1024)

// ---------------- scratch (static device globals; no runtime alloc) --------
__device__ __half g_hA[GN * 64];    // half gather source (gemm0 out, later gemm2 out)
__device__ __half g_hy0[GN * 64];   // half y0 (layer-0 pre-BN output)
__device__ float  g_bufA[GN * 64];  // fp32 aggregate (gather output -> gemm input)
__device__ float  g_bufB[GN * 64];  // fp32 y1
__device__ float  g_out_isqrt[GN];
__device__ float  g_in_isqrt[GN];
// stats: layer0 sum [0:64) sumsq [64:128); layer1 sum [128:192) sumsq [192:256)
__device__ float  g_stats[256];
__device__ int    g_cnt_in[GN];
__device__ int    g_cnt_out[GN];
__device__ int    g_row[GN + 1];
__device__ int    g_col[GE];
__device__ int    g_fill[GN];
__device__ int    g_bsum[128];

// ---------------- zero helper ----------------
__global__ void k_zero_int() {
    int i = blockIdx.x * blockDim.x + threadIdx.x;
    if (i < GN) { g_cnt_in[i] = 0; g_cnt_out[i] = 0; }
}

// ---------------- degree counts: 4 edges per thread via int4 --------------
__global__ void k_count(const int* __restrict__ src,
                        const int* __restrict__ dst) {
    int t = blockIdx.x * blockDim.x + threadIdx.x;
    if (t >= GE / 4) return;
    int4 sv = __ldg((const int4*)&src[4 * t]);
    int4 dv = __ldg((const int4*)&dst[4 * t]);
    if ((unsigned)sv.x < GN) atomicAdd(&g_cnt_out[sv.x], 1);
    if ((unsigned)sv.y < GN) atomicAdd(&g_cnt_out[sv.y], 1);
    if ((unsigned)sv.z < GN) atomicAdd(&g_cnt_out[sv.z], 1);
    if ((unsigned)sv.w < GN) atomicAdd(&g_cnt_out[sv.w], 1);
    if ((unsigned)dv.x < GN) atomicAdd(&g_cnt_in[dv.x], 1);
    if ((unsigned)dv.y < GN) atomicAdd(&g_cnt_in[dv.y], 1);
    if ((unsigned)dv.z < GN) atomicAdd(&g_cnt_in[dv.z], 1);
    if ((unsigned)dv.w < GN) atomicAdd(&g_cnt_in[dv.w], 1);
}

// ---------------- CSR scan pass 1: per-block sums ----------------
__global__ void k_scan_part() {
    __shared__ int red[1024];
    int gid = blockIdx.x * 1024 + threadIdx.x;
    int v = (gid < GN) ? g_cnt_in[gid] : 0;
    red[threadIdx.x] = v;
    __syncthreads();
    for (int s = 512; s > 0; s >>= 1) {
        if (threadIdx.x < s) red[threadIdx.x] += red[threadIdx.x + s];
        __syncthreads();
    }
    if (threadIdx.x == 0) g_bsum[blockIdx.x] = red[0];
}

// ---------------- CSR scan pass 2: final scan; block-prefix computed here --
// (replaces the old k_scan_mid launch) + fused degree-isqrt + fill cursors
__global__ void k_scan_final() {
    __shared__ int s[1024];
    __shared__ int spre[128];
    int t = threadIdx.x;
    // exclusive prefix of g_bsum over blocks < blockIdx.x (tree-reduce 128)
    if (t < 128) {
        int v = (t < NB_SCAN) ? g_bsum[t] : 0;
        spre[t] = (t < (int)blockIdx.x) ? v : 0;
    }
    __syncthreads();
    for (int off = 64; off > 0; off >>= 1) {
        if (t < off) spre[t] += spre[t + off];
        __syncthreads();
    }
    int base_prefix = spre[0];

    int gid = blockIdx.x * 1024 + t;
    int v = (gid < GN) ? g_cnt_in[gid] : 0;
    s[t] = v;
    __syncthreads();
    for (int off = 1; off < 1024; off <<= 1) {
        int tmp = (t >= off) ? s[t - off] : 0;
        __syncthreads();
        s[t] += tmp;
        __syncthreads();
    }
    if (gid < GN) {
        int r = s[t] - v + base_prefix;
        g_row[gid]  = r;
        g_fill[gid] = r;
        g_in_isqrt[gid]  = rsqrtf(fmaxf((float)v, 1.0f));
        g_out_isqrt[gid] = rsqrtf(fmaxf((float)g_cnt_out[gid], 1.0f));
    }
    if (blockIdx.x == NB_SCAN - 1 && t == 1023) g_row[GN] = base_prefix + s[1023];
}

// ---------------- fill: 4 edges per thread via int4 ----------------
__global__ void k_fill(const int* __restrict__ src,
                       const int* __restrict__ dst) {
    int t = blockIdx.x * blockDim.x + threadIdx.x;
    if (t >= GE / 4) return;
    int4 sv = __ldg((const int4*)&src[4 * t]);
    int4 dv = __ldg((const int4*)&dst[4 * t]);
    if ((unsigned)sv.x < GN && (unsigned)dv.x < GN)
        g_col[atomicAdd(&g_fill[dv.x], 1)] = sv.x;
    if ((unsigned)sv.y < GN && (unsigned)dv.y < GN)
        g_col[atomicAdd(&g_fill[dv.y], 1)] = sv.y;
    if ((unsigned)sv.z < GN && (unsigned)dv.z < GN)
        g_col[atomicAdd(&g_fill[dv.z], 1)] = sv.z;
    if ((unsigned)sv.w < GN && (unsigned)dv.w < GN)
        g_col[atomicAdd(&g_fill[dv.w], 1)] = sv.w;
}

// ---------------- GEMM0: feat @ W0  [128 -> 64] -> g_hA (UNscaled) --------
// out_isqrt applied per-source in the gather. Runs overlapped with CSR build.
// Also zeroes ALL 256 stats accumulators (block 0).
__global__ void k_gemm0(const float* __restrict__ feat,
                        const float* __restrict__ W) {
    __shared__ float sAT[16][132];
    __shared__ float sW[16][64];
    int base = blockIdx.x * 128;
    if (blockIdx.x == 0) g_stats[threadIdx.x] = 0.0f;   // 256 threads -> all 256
    int cgi = threadIdx.x & 15;
    int ngi = threadIdx.x >> 4;
    int cg = cgi * 4;
    float acc[8][4] = {};
    for (int kb = 0; kb < 8; kb++) {
        __syncthreads();
        #pragma unroll
        for (int it = 0; it < 2; it++) {
            int task = threadIdx.x + 256 * it;
            int node = task >> 2, k4 = task & 3;
            int gnode = base + node;
            float4 v = make_float4(0.f, 0.f, 0.f, 0.f);
            if (gnode < GN)
                v = __ldg((const float4*)&feat[gnode * 128 + kb * 16 + k4 * 4]);
            sAT[4 * k4 + 0][node] = v.x;
            sAT[4 * k4 + 1][node] = v.y;
            sAT[4 * k4 + 2][node] = v.z;
            sAT[4 * k4 + 3][node] = v.w;
        }
        {
            int kk = threadIdx.x >> 4, c4 = threadIdx.x & 15;
            *(float4*)&sW[kk][c4 * 4] =
                __ldg((const float4*)&W[(kb * 16 + kk) * 64 + c4 * 4]);
        }
        __syncthreads();
        #pragma unroll
        for (int kk = 0; kk < 16; kk++) {
            float4 a0 = *(const float4*)&sAT[kk][ngi * 8];
            float4 a1 = *(const float4*)&sAT[kk][ngi * 8 + 4];
            float4 w  = *(const float4*)&sW[kk][cg];
            float av[8] = {a0.x, a0.y, a0.z, a0.w, a1.x, a1.y, a1.z, a1.w};
            #pragma unroll
            for (int i = 0; i < 8; i++) {
                acc[i][0] += av[i] * w.x;
                acc[i][1] += av[i] * w.y;
                acc[i][2] += av[i] * w.z;
                acc[i][3] += av[i] * w.w;
            }
        }
    }
    #pragma unroll
    for (int i = 0; i < 8; i++) {
        int node = base + ngi * 8 + i;
        if (node < GN) {
            __half2 h0 = __floats2half2_rn(acc[i][0], acc[i][1]);
            __half2 h1 = __floats2half2_rn(acc[i][2], acc[i][3]);
            uint2 pk;
            pk.x = *(unsigned int*)&h0;
            pk.y = *(unsigned int*)&h1;
            *(uint2*)&g_hA[node * 64 + cg] = pk;
        }
    }
}

// ---------------- gather, 64 feats (half src, *os[src]), layer0 epilogue --
// g_hA -> g_hy0 (+BN stats into g_stats[0:128))
__global__ void k_gather64_l0(const float* __restrict__ bias) {
    __shared__ float s_s[64], s_q[64];
    if (threadIdx.x < 64) { s_s[threadIdx.x] = 0.0f; s_q[threadIdx.x] = 0.0f; }
    __syncthreads();
    int node = blockIdx.x * 8 + (threadIdx.x >> 5);
    int lane = threadIdx.x & 31;
    if (node < GN) {
        int beg = g_row[node], end = g_row[node + 1];
        float ax0 = 0, ay0 = 0, ax1 = 0, ay1 = 0, ax2 = 0, ay2 = 0, ax3 = 0, ay3 = 0;
        int e = beg;
        for (; e + 3 < end; e += 4) {
            int s0 = __ldg(&g_col[e]);
            int s1 = __ldg(&g_col[e + 1]);
            int s2 = __ldg(&g_col[e + 2]);
            int s3 = __ldg(&g_col[e + 3]);
            float o0 = __ldg(&g_out_isqrt[s0]);
            float o1 = __ldg(&g_out_isqrt[s1]);
            float o2 = __ldg(&g_out_isqrt[s2]);
            float o3 = __ldg(&g_out_isqrt[s3]);
            float2 v0 = __half22float2(*(const __half2*)&g_hA[s0 * 64 + 2 * lane]);
            float2 v1 = __half22float2(*(const __half2*)&g_hA[s1 * 64 + 2 * lane]);
            float2 v2 = __half22float2(*(const __half2*)&g_hA[s2 * 64 + 2 * lane]);
            float2 v3 = __half22float2(*(const __half2*)&g_hA[s3 * 64 + 2 * lane]);
            ax0 += v0.x * o0; ay0 += v0.y * o0;
            ax1 += v1.x * o1; ay1 += v1.y * o1;
            ax2 += v2.x * o2; ay2 += v2.y * o2;
            ax3 += v3.x * o3; ay3 += v3.y * o3;
        }
        for (; e < end; e++) {
            int s0 = __ldg(&g_col[e]);
            float o0 = __ldg(&g_out_isqrt[s0]);
            float2 v0 = __half22float2(*(const __half2*)&g_hA[s0 * 64 + 2 * lane]);
            ax0 += v0.x * o0; ay0 += v0.y * o0;
        }
        float ax = (ax0 + ax1) + (ax2 + ax3);
        float ay = (ay0 + ay1) + (ay2 + ay3);
        float isq = g_in_isqrt[node];
        float v0 = ax * isq + __ldg(&bias[2 * lane]);
        float v1 = ay * isq + __ldg(&bias[2 * lane + 1]);
        *(__half2*)&g_hy0[node * 64 + 2 * lane] = __floats2half2_rn(v0, v1);
        atomicAdd(&s_s[2 * lane], v0);      atomicAdd(&s_s[2 * lane + 1], v1);
        atomicAdd(&s_q[2 * lane], v0 * v0); atomicAdd(&s_q[2 * lane + 1], v1 * v1);
    }
    __syncthreads();
    if (threadIdx.x < 64) {
        atomicAdd(&g_stats[threadIdx.x],      s_s[threadIdx.x]);
        atomicAdd(&g_stats[64 + threadIdx.x], s_q[threadIdx.x]);
    }
}

// ---------------- gather64 w/ inline BN0 finalize + ReLU + os[src] --------
// g_hy0 -> bufA (fp32).  sc/sh computed per-thread from raw layer0 sums.
__global__ void k_gather64_bn(const float* __restrict__ gamma,
                              const float* __restrict__ beta) {
    int node = blockIdx.x * 8 + (threadIdx.x >> 5);
    int lane = threadIdx.x & 31;
    if (node >= GN) return;
    const float inv_n = 1.0f / (float)GN;
    int f0 = 2 * lane, f1 = 2 * lane + 1;
    float mu0 = __ldg(&g_stats[f0]) * inv_n;
    float mu1 = __ldg(&g_stats[f1]) * inv_n;
    float var0 = __ldg(&g_stats[64 + f0]) * inv_n - mu0 * mu0;
    float var1 = __ldg(&g_stats[64 + f1]) * inv_n - mu1 * mu1;
    float sc0 = __ldg(&gamma[f0]) * rsqrtf(var0 + EPS);
    float sc1 = __ldg(&gamma[f1]) * rsqrtf(var1 + EPS);
    float sh0 = __ldg(&beta[f0]) - mu0 * sc0;
    float sh1 = __ldg(&beta[f1]) - mu1 * sc1;
    int beg = g_row[node], end = g_row[node + 1];
    float ax0 = 0, ay0 = 0, ax1 = 0, ay1 = 0, ax2 = 0, ay2 = 0, ax3 = 0, ay3 = 0;
    int e = beg;
    for (; e + 3 < end; e += 4) {
        int s0 = __ldg(&g_col[e]);
        int s1 = __ldg(&g_col[e + 1]);
        int s2 = __ldg(&g_col[e + 2]);
        int s3 = __ldg(&g_col[e + 3]);
        float o0 = __ldg(&g_out_isqrt[s0]);
        float o1 = __ldg(&g_out_isqrt[s1]);
        float o2 = __ldg(&g_out_isqrt[s2]);
        float o3 = __ldg(&g_out_isqrt[s3]);
        float2 v0 = __half22float2(*(const __half2*)&g_hy0[s0 * 64 + 2 * lane]);
        float2 v1 = __half22float2(*(const __half2*)&g_hy0[s1 * 64 + 2 * lane]);
        float2 v2 = __half22float2(*(const __half2*)&g_hy0[s2 * 64 + 2 * lane]);
        float2 v3 = __half22float2(*(const __half2*)&g_hy0[s3 * 64 + 2 * lane]);
        ax0 += fmaxf(v0.x * sc0 + sh0, 0.0f) * o0;
        ay0 += fmaxf(v0.y * sc1 + sh1, 0.0f) * o0;
        ax1 += fmaxf(v1.x * sc0 + sh0, 0.0f) * o1;
        ay1 += fmaxf(v1.y * sc1 + sh1, 0.0f) * o1;
        ax2 += fmaxf(v2.x * sc0 + sh0, 0.0f) * o2;
        ay2 += fmaxf(v2.y * sc1 + sh1, 0.0f) * o2;
        ax3 += fmaxf(v3.x * sc0 + sh0, 0.0f) * o3;
        ay3 += fmaxf(v3.y * sc1 + sh1, 0.0f) * o3;
    }
    for (; e < end; e++) {
        int s0 = __ldg(&g_col[e]);
        float o0 = __ldg(&g_out_isqrt[s0]);
        float2 v0 = __half22float2(*(const __half2*)&g_hy0[s0 * 64 + 2 * lane]);
        ax0 += fmaxf(v0.x * sc0 + sh0, 0.0f) * o0;
        ay0 += fmaxf(v0.y * sc1 + sh1, 0.0f) * o0;
    }
    float ax = (ax0 + ax1) + (ax2 + ax3);
    float ay = (ay0 + ay1) + (ay2 + ay3);
    *(float2*)&g_bufA[node * 64 + 2 * lane] = make_float2(ax, ay);
}

// ---------------- GEMM1: bufA @ W1 then *in_isqrt + b1 -> bufB ------------
// BN stats accumulated into g_stats[128:256)
__global__ void k_gemm1_stats(const float* __restrict__ W,
                              const float* __restrict__ bias) {
    __shared__ float sAT[16][132];
    __shared__ float sW[16][64];
    __shared__ float s_isq[128];
    __shared__ float s_s[64], s_q[64];
    int base = blockIdx.x * 128;
    for (int i = threadIdx.x; i < 128; i += 256) {
        int node = base + i;
        s_isq[i] = (node < GN) ? g_in_isqrt[node] : 0.0f;
    }
    if (threadIdx.x < 64) { s_s[threadIdx.x] = 0.0f; s_q[threadIdx.x] = 0.0f; }
    int cgi = threadIdx.x & 15;
    int ngi = threadIdx.x >> 4;
    int cg = cgi * 4;
    float acc[8][4] = {};
    for (int kb = 0; kb < 4; kb++) {
        __syncthreads();
        #pragma unroll
        for (int it = 0; it < 2; it++) {
            int task = threadIdx.x + 256 * it;
            int node = task >> 2, k4 = task & 3;
            int gnode = base + node;
            float4 v = make_float4(0.f, 0.f, 0.f, 0.f);
            if (gnode < GN)
                v = *(const float4*)&g_bufA[gnode * 64 + kb * 16 + k4 * 4];
            sAT[4 * k4 + 0][node] = v.x;
            sAT[4 * k4 + 1][node] = v.y;
            sAT[4 * k4 + 2][node] = v.z;
            sAT[4 * k4 + 3][node] = v.w;
        }
        {
            int kk = threadIdx.x >> 4, c4 = threadIdx.x & 15;
            *(float4*)&sW[kk][c4 * 4] =
                __ldg((const float4*)&W[(kb * 16 + kk) * 64 + c4 * 4]);
        }
        __syncthreads();
        #pragma unroll
        for (int kk = 0; kk < 16; kk++) {
            float4 a0 = *(const float4*)&sAT[kk][ngi * 8];
            float4 a1 = *(const float4*)&sAT[kk][ngi * 8 + 4];
            float4 w  = *(const float4*)&sW[kk][cg];
            float av[8] = {a0.x, a0.y, a0.z, a0.w, a1.x, a1.y, a1.z, a1.w};
            #pragma unroll
            for (int i = 0; i < 8; i++) {
                acc[i][0] += av[i] * w.x;
                acc[i][1] += av[i] * w.y;
                acc[i][2] += av[i] * w.z;
                acc[i][3] += av[i] * w.w;
            }
        }
    }
    float4 bv = __ldg((const float4*)&bias[cg]);
    float ls[4] = {}, lq[4] = {};
    #pragma unroll
    for (int i = 0; i < 8; i++) {
        int node = base + ngi * 8 + i;
        if (node < GN) {
            float is = s_isq[ngi * 8 + i];
            float v0 = acc[i][0] * is + bv.x;
            float v1 = acc[i][1] * is + bv.y;
            float v2 = acc[i][2] * is + bv.z;
            float v3 = acc[i][3] * is + bv.w;
            *(float4*)&g_bufB[node * 64 + cg] = make_float4(v0, v1, v2, v3);
            ls[0] += v0; lq[0] += v0 * v0;
            ls[1] += v1; lq[1] += v1 * v1;
            ls[2] += v2; lq[2] += v2 * v2;
            ls[3] += v3; lq[3] += v3 * v3;
        }
    }
    #pragma unroll
    for (int j = 0; j < 4; j++) {
        atomicAdd(&s_s[cg + j], ls[j]);
        atomicAdd(&s_q[cg + j], lq[j]);
    }
    __syncthreads();
    if (threadIdx.x < 64) {
        atomicAdd(&g_stats[128 + threadIdx.x], s_s[threadIdx.x]);
        atomicAdd(&g_stats[192 + threadIdx.x], s_q[threadIdx.x]);
    }
}

// ---------------- GEMM2: t1(bufB) @ W2  [64 -> 47] -> g_hA (stride 64) -----
// BN1 finalize computed inline from raw layer1 sums (g_stats[128:256))
__global__ void k_gemm2_bn(const float* __restrict__ W,
                           const float* __restrict__ gamma,
                           const float* __restrict__ beta) {
    __shared__ float sAT[16][132];
    __shared__ float sW[16][64];
    __shared__ float s_os[128];
    __shared__ float s_sc[64], s_sh[64];
    int base = blockIdx.x * 128;
    for (int i = threadIdx.x; i < 128; i += 256) {
        int node = base + i;
        s_os[i] = (node < GN) ? g_out_isqrt[node] : 0.0f;
    }
    if (threadIdx.x < 64) {
        const float inv_n = 1.0f / (float)GN;
        int f = threadIdx.x;
        float mu = __ldg(&g_stats[128 + f]) * inv_n;
        float var = __ldg(&g_stats[192 + f]) * inv_n - mu * mu;
        float sc = __ldg(&gamma[f]) * rsqrtf(var + EPS);
        s_sc[f] = sc;
        s_sh[f] = __ldg(&beta[f]) - mu * sc;
    }
    int cgi = threadIdx.x & 15;
    int ngi = threadIdx.x >> 4;
    int cg = cgi * 4;
    float acc[8][4] = {};
    for (int kb = 0; kb < 4; kb++) {
        __syncthreads();
        #pragma unroll
        for (int it = 0; it < 2; it++) {
            int task = threadIdx.x + 256 * it;
            int node = task >> 2, k4 = task & 3;
            int gnode = base + node;
            float4 v = make_float4(0.f, 0.f, 0.f, 0.f);
            if (gnode < GN)
                v = *(const float4*)&g_bufB[gnode * 64 + kb * 16 + k4 * 4];
            float os = s_os[node];
            int k = kb * 16 + 4 * k4;
            sAT[4 * k4 + 0][node] = fmaxf(v.x * s_sc[k]     + s_sh[k],     0.0f) * os;
            sAT[4 * k4 + 1][node] = fmaxf(v.y * s_sc[k + 1] + s_sh[k + 1], 0.0f) * os;
            sAT[4 * k4 + 2][node] = fmaxf(v.z * s_sc[k + 2] + s_sh[k + 2], 0.0f) * os;
            sAT[4 * k4 + 3][node] = fmaxf(v.w * s_sc[k + 3] + s_sh[k + 3], 0.0f) * os;
        }
        #pragma unroll
        for (int it = 0; it < 4; it++) {
            int i = threadIdx.x + 256 * it;
            int kk = i >> 6, c = i & 63;
            float w = 0.0f;
            if (c < 47) w = __ldg(&W[(kb * 16 + kk) * 47 + c]);
            sW[kk][c] = w;
        }
        __syncthreads();
        #pragma unroll
        for (int kk = 0; kk < 16; kk++) {
            float4 a0 = *(const float4*)&sAT[kk][ngi * 8];
            float4 a1 = *(const float4*)&sAT[kk][ngi * 8 + 4];
            float4 w  = *(const float4*)&sW[kk][cg];
            float av[8] = {a0.x, a0.y, a0.z, a0.w, a1.x, a1.y, a1.z, a1.w};
            #pragma unroll
            for (int i = 0; i < 8; i++) {
                acc[i][0] += av[i] * w.x;
                acc[i][1] += av[i] * w.y;
                acc[i][2] += av[i] * w.z;
                acc[i][3] += av[i] * w.w;
            }
        }
    }
    #pragma unroll
    for (int i = 0; i < 8; i++) {
        int node = base + ngi * 8 + i;
        if (node < GN) {
            __half2 h0 = __floats2half2_rn(acc[i][0], acc[i][1]);
            __half2 h1 = __floats2half2_rn(acc[i][2], acc[i][3]);
            uint2 pk;
            pk.x = *(unsigned int*)&h0;
            pk.y = *(unsigned int*)&h1;
            *(uint2*)&g_hA[node * 64 + cg] = pk;
        }
    }
}

// ---------------- gather, 47 feats (half src) + final epilogue -> out -----
__global__ void k_gather47(const float* __restrict__ b2,
                           float* __restrict__ out) {
    int node = blockIdx.x * 8 + (threadIdx.x >> 5);
    int lane = threadIdx.x & 31;
    if (node >= GN) return;
    int beg = g_row[node], end = g_row[node + 1];
    int f = 2 * lane;
    float ax0 = 0, ay0 = 0, ax1 = 0, ay1 = 0, ax2 = 0, ay2 = 0, ax3 = 0, ay3 = 0;
    if (f < 46) {
        int e = beg;
        for (; e + 3 < end; e += 4) {
            int s0 = __ldg(&g_col[e]);
            int s1 = __ldg(&g_col[e + 1]);
            int s2 = __ldg(&g_col[e + 2]);
            int s3 = __ldg(&g_col[e + 3]);
            float2 v0 = __half22float2(*(const __half2*)&g_hA[s0 * 64 + f]);
            float2 v1 = __half22float2(*(const __half2*)&g_hA[s1 * 64 + f]);
            float2 v2 = __half22float2(*(const __half2*)&g_hA[s2 * 64 + f]);
            float2 v3 = __half22float2(*(const __half2*)&g_hA[s3 * 64 + f]);
            ax0 += v0.x; ay0 += v0.y;
            ax1 += v1.x; ay1 += v1.y;
            ax2 += v2.x; ay2 += v2.y;
            ax3 += v3.x; ay3 += v3.y;
        }
        for (; e < end; e++) {
            int s0 = __ldg(&g_col[e]);
            float2 v0 = __half22float2(*(const __half2*)&g_hA[s0 * 64 + f]);
            ax0 += v0.x; ay0 += v0.y;
        }
        float isq = g_in_isqrt[node];
        out[node * 47 + f]     = ((ax0 + ax1) + (ax2 + ax3)) * isq + __ldg(&b2[f]);
        out[node * 47 + f + 1] = ((ay0 + ay1) + (ay2 + ay3)) * isq + __ldg(&b2[f + 1]);
    } else if (f == 46) {
        for (int e = beg; e < end; e++) {
            int s = __ldg(&g_col[e]);
            ax0 += __half2float(g_hA[s * 64 + 46]);
        }
        out[node * 47 + 46] = ax0 * g_in_isqrt[node] + __ldg(&b2[46]);
    }
}

// ============================================================================
extern "C" void kernel_launch(void* const* d_in, const int* in_sizes, int n_in,
                              void* d_out, int out_size) {
    const float* feat = (const float*)d_in[0];
    const int*   src  = (const int*)d_in[1];    // int32 (jax x64 disabled)
    const int*   dst  = (const int*)d_in[2];
    const float* W0 = (const float*)d_in[3];
    const float* b0 = (const float*)d_in[4];
    const float* W1 = (const float*)d_in[5];
    const float* b1 = (const float*)d_in[6];
    const float* W2 = (const float*)d_in[7];
    const float* b2 = (const float*)d_in[8];
    const float* gamma0 = (const float*)d_in[9];
    const float* beta0  = (const float*)d_in[10];
    const float* gamma1 = (const float*)d_in[11];
    const float* beta1  = (const float*)d_in[12];
    float* out = (float*)d_out;

    const int GB = 12500;              // gather blocks: 8 nodes each
    const int MB = (GN + 127) / 128;   // gemm blocks: 128 nodes each
    const int EB4 = (GE / 4 + 255) / 256;  // 4-edges-per-thread blocks

    // side stream + events (created once on the uncaptured correctness call)
    static cudaStream_t s_side = nullptr;
    static cudaEvent_t  s_ev0 = nullptr, s_ev1 = nullptr;
    if (s_side == nullptr) {
        cudaStreamCreateWithFlags(&s_side, cudaStreamNonBlocking);
        cudaEventCreateWithFlags(&s_ev0, cudaEventDisableTiming);
        cudaEventCreateWithFlags(&s_ev1, cudaEventDisableTiming);
    }

    // ---- fork: gemm0 (feat-only) on side stream, CSR build on main ----
    cudaEventRecord(s_ev0, 0);
    cudaStreamWaitEvent(s_side, s_ev0, 0);
    k_gemm0<<<MB, 256, 0, s_side>>>(feat, W0);   // feat -> g_hA (+zero stats)
    cudaEventRecord(s_ev1, s_side);

    // ---- CSR build + degree isqrt (main stream) ----
    k_zero_int<<<(GN + 255) / 256, 256>>>();
    k_count<<<EB4, 256>>>(src, dst);
    k_scan_part<<<NB_SCAN, 1024>>>();
    k_scan_final<<<NB_SCAN, 1024>>>();      // block-prefix inline; isqrt + cursors
    k_fill<<<EB4, 256>>>(src, dst);

    // ---- join: gather needs both CSR and gemm0 output ----
    cudaStreamWaitEvent(0, s_ev1, 0);

    // ---- layer 0: gather w/ fused os[src]+bias+stats epilogue ----
    k_gather64_l0<<<GB, 256>>>(b0);              // g_hA -> g_hy0 (y0 + stats)

    // ---- layer 1: gather w/ inline BN0 finalize, matmul (64 -> 64) ----
    k_gather64_bn<<<GB, 256>>>(gamma0, beta0);   // g_hy0 -> bufA
    k_gemm1_stats<<<MB, 256>>>(W1, b1);          // bufA -> bufB (y1 + stats)

    // ---- layer 2: matmul w/ inline BN1 finalize (64 -> 47), gather ----
    k_gemm2_bn<<<MB, 256>>>(W2, gamma1, beta1);  // bufB -> g_hA (stride 64)
    k_gather47<<<GB, 256>>>(b2, out);            // g_hA -> out
}